// round 6
// baseline (speedup 1.0000x reference)
#include <cuda_runtime.h>
#include <cuda_bf16.h>
#include <math.h>
#include <stdint.h>

// ---------------------------------------------------------------------------
// Problem constants
// ---------------------------------------------------------------------------
#define Nn   16
#define Cc   256
#define Hh   64
#define Ww   64
#define PP   66                       // padded spatial (1 halo each side)
#define NPIX (Cc*Hh*Ww)               // per-sample elements (GroupNorm group)
#define XQTOT (Nn*PP*PP*Cc)           // NHWC padded bf16 activations
#define WTOT (Cc*Cc*9)
#define GN_EPSF 1e-5f

// ---------------------------------------------------------------------------
// Scratch (__device__ globals; no allocation anywhere)
// ---------------------------------------------------------------------------
__device__ __align__(1024) __nv_bfloat16 g_xq[XQTOT];   // [n][ph][pw][ic]
__device__ __align__(1024) __nv_bfloat16 g_wq[WTOT];    // [tap][ic][oc], {-1,0,1}
__device__ double g_sum[Nn];
__device__ double g_sumsq[Nn];
__device__ double g_wabs;
__device__ unsigned int g_maxbits;
__device__ float g_meanf[Nn], g_istdf[Nn];
__device__ float g_qscale;   // 128 / gamma
__device__ float g_coef;     // 0.01 * gamma / 128
__device__ float g_delta;    // 0.7 * mean|w|

// ---------------------------------------------------------------------------
// Portable PTX helpers (sm_80+ only; must compile under plain sm_100)
// ---------------------------------------------------------------------------
__device__ __forceinline__ uint32_t smem_u32(const void* p) {
    uint32_t a;
    asm("{ .reg .u64 t; cvta.to.shared.u64 t, %1; cvt.u32.u64 %0, t; }" : "=r"(a) : "l"(p));
    return a;
}
__device__ __forceinline__ void cp16(uint32_t dst, const void* src) {
    asm volatile("cp.async.cg.shared.global [%0], [%1], 16;" :: "r"(dst), "l"(src) : "memory");
}
__device__ __forceinline__ void cp_commit() {
    asm volatile("cp.async.commit_group;" ::: "memory");
}
__device__ __forceinline__ void ldsm_x4(uint32_t a, uint32_t& r0, uint32_t& r1,
                                        uint32_t& r2, uint32_t& r3) {
    asm volatile("ldmatrix.sync.aligned.m8n8.x4.shared.b16 {%0,%1,%2,%3}, [%4];"
                 : "=r"(r0), "=r"(r1), "=r"(r2), "=r"(r3) : "r"(a));
}
__device__ __forceinline__ void ldsm_x4t(uint32_t a, uint32_t& r0, uint32_t& r1,
                                         uint32_t& r2, uint32_t& r3) {
    asm volatile("ldmatrix.sync.aligned.m8n8.x4.trans.shared.b16 {%0,%1,%2,%3}, [%4];"
                 : "=r"(r0), "=r"(r1), "=r"(r2), "=r"(r3) : "r"(a));
}
__device__ __forceinline__ void mma16816(float* d, const uint32_t* a,
                                         uint32_t b0, uint32_t b1) {
    asm volatile(
        "mma.sync.aligned.m16n8k16.row.col.f32.bf16.bf16.f32 "
        "{%0,%1,%2,%3}, {%4,%5,%6,%7}, {%8,%9}, {%0,%1,%2,%3};"
        : "+f"(d[0]), "+f"(d[1]), "+f"(d[2]), "+f"(d[3])
        : "r"(a[0]), "r"(a[1]), "r"(a[2]), "r"(a[3]), "r"(b0), "r"(b1));
}

// ---------------------------------------------------------------------------
// K0: zero reduction scratch
// ---------------------------------------------------------------------------
__global__ void k_init() {
    int t = threadIdx.x;
    if (t < Nn) { g_sum[t] = 0.0; g_sumsq[t] = 0.0; }
    if (t == 0) { g_wabs = 0.0; g_maxbits = 0u; }
}

// ---------------------------------------------------------------------------
// K1: per-sample sum / sumsq
// ---------------------------------------------------------------------------
__global__ void k_stats(const float* __restrict__ x) {
    int n = blockIdx.y;
    const float* p = x + (size_t)n * NPIX + (size_t)blockIdx.x * 16384;
    int tid = threadIdx.x;
    float s = 0.f, ss = 0.f;
#pragma unroll
    for (int k = 0; k < 16; k++) {
        float4 v = *(const float4*)(p + tid * 4 + k * 1024);
        s  += v.x + v.y + v.z + v.w;
        ss += v.x*v.x + v.y*v.y + v.z*v.z + v.w*v.w;
    }
#pragma unroll
    for (int off = 16; off; off >>= 1) {
        s  += __shfl_xor_sync(0xffffffffu, s,  off);
        ss += __shfl_xor_sync(0xffffffffu, ss, off);
    }
    __shared__ double ws[8], wss[8];
    int wid = tid >> 5, lane = tid & 31;
    if (lane == 0) { ws[wid] = (double)s; wss[wid] = (double)ss; }
    __syncthreads();
    if (tid == 0) {
        double S = 0.0, SS = 0.0;
#pragma unroll
        for (int i = 0; i < 8; i++) { S += ws[i]; SS += wss[i]; }
        atomicAdd(&g_sum[n], S);
        atomicAdd(&g_sumsq[n], SS);
    }
}

// ---------------------------------------------------------------------------
// K1w: sum |w|
// ---------------------------------------------------------------------------
__global__ void k_wabs(const float* __restrict__ w) {
    int tid = threadIdx.x;
    float s = 0.f;
    for (int i = blockIdx.x * 256 + tid; i < WTOT; i += gridDim.x * 256)
        s += fabsf(w[i]);
#pragma unroll
    for (int off = 16; off; off >>= 1) s += __shfl_xor_sync(0xffffffffu, s, off);
    __shared__ double ws[8];
    int wid = tid >> 5, lane = tid & 31;
    if (lane == 0) ws[wid] = (double)s;
    __syncthreads();
    if (tid == 0) {
        double S = 0.0;
#pragma unroll
        for (int i = 0; i < 8; i++) S += ws[i];
        atomicAdd(&g_wabs, S);
    }
}

__device__ __forceinline__ void sample_stats(int n, float& fm, float& istd) {
    double S = g_sum[n], SS = g_sumsq[n];
    double m = S * (1.0 / (double)NPIX);
    double v = SS * (1.0 / (double)NPIX) - m * m;
    fm = (float)m;
    istd = 1.0f / sqrtf((float)v + GN_EPSF);
}

// ---------------------------------------------------------------------------
// K2: global max |groupnorm(x)|
// ---------------------------------------------------------------------------
__global__ void k_max(const float* __restrict__ x,
                      const float* __restrict__ lnw,
                      const float* __restrict__ lnb) {
    int n = blockIdx.y;
    float fm, istd;
    sample_stats(n, fm, istd);
    const float* p = x + (size_t)n * NPIX + (size_t)blockIdx.x * 16384;
    int base = blockIdx.x * 16384;
    int tid = threadIdx.x;
    float m = 0.f;
#pragma unroll
    for (int k = 0; k < 16; k++) {
        int i = base + tid * 4 + k * 1024;
        int c = i >> 12;
        float g = lnw[c], b = lnb[c];
        float4 v = *(const float4*)(p + tid * 4 + k * 1024);
        m = fmaxf(m, fabsf(((v.x - fm) * istd) * g + b));
        m = fmaxf(m, fabsf(((v.y - fm) * istd) * g + b));
        m = fmaxf(m, fabsf(((v.z - fm) * istd) * g + b));
        m = fmaxf(m, fabsf(((v.w - fm) * istd) * g + b));
    }
#pragma unroll
    for (int off = 16; off; off >>= 1) m = fmaxf(m, __shfl_xor_sync(0xffffffffu, m, off));
    __shared__ float wm[8];
    int wid = tid >> 5, lane = tid & 31;
    if (lane == 0) wm[wid] = m;
    __syncthreads();
    if (tid == 0) {
#pragma unroll
        for (int i = 1; i < 8; i++) m = fmaxf(m, wm[i]);
        atomicMax(&g_maxbits, __float_as_uint(m));
    }
}

// ---------------------------------------------------------------------------
// K2b: finalize scalars
// ---------------------------------------------------------------------------
__global__ void k_post() {
    int t = threadIdx.x;
    if (t < Nn) {
        float fm, istd;
        sample_stats(t, fm, istd);
        g_meanf[t] = fm;
        g_istdf[t] = istd;
    }
    if (t == 0) {
        float gamma = fmaxf(__uint_as_float(g_maxbits), 1e-6f);
        g_qscale = 128.0f / gamma;
        g_coef = 0.01f * gamma * (1.0f / 128.0f);
        g_delta = 0.7f * (float)(g_wabs * (1.0 / (double)WTOT));
    }
}

// ---------------------------------------------------------------------------
// K3a: zero the halo of g_xq
// ---------------------------------------------------------------------------
__global__ void k_halo() {
    int idx = blockIdx.x * 256 + threadIdx.x;       // 520 blocks
    int n = idx / (260 * 32);
    int r = idx - n * (260 * 32);
    int p = r >> 5, q = r & 31;
    int ph, pw;
    if (p < 66)       { ph = 0;       pw = p; }
    else if (p < 132) { ph = 65;      pw = p - 66; }
    else if (p < 196) { ph = p - 131; pw = 0; }
    else              { ph = p - 195; pw = 65; }
    uint4 z = make_uint4(0, 0, 0, 0);
    *(uint4*)(g_xq + ((size_t)(n * PP + ph) * PP + pw) * Cc + q * 8) = z;
}

// ---------------------------------------------------------------------------
// K3: quantize + NCHW->NHWC transpose into padded bf16 scratch
// ---------------------------------------------------------------------------
__global__ void k_quant_t(const float* __restrict__ x,
                          const float* __restrict__ lnw,
                          const float* __restrict__ lnb) {
    __shared__ float sm[64][68];
    int b = blockIdx.x;
    int ic4 = b & 3, h = (b >> 2) & 63, n = b >> 8;
    int tid = threadIdx.x;
    float mean = g_meanf[n], istd = g_istdf[n], qs = g_qscale;

    const float* xb = x + ((size_t)n * Cc + ic4 * 64) * 4096 + h * 64;
#pragma unroll
    for (int i = tid; i < 1024; i += 256) {
        int row = i >> 4, c4 = i & 15;
        float4 v = *(const float4*)(xb + (size_t)row * 4096 + c4 * 4);
        *(float4*)&sm[row][c4 * 4] = v;
    }
    __syncthreads();

    __nv_bfloat16* ob = g_xq + ((size_t)(n * PP + h + 1) * PP + 1) * Cc + ic4 * 64;
#pragma unroll
    for (int j = tid; j < 512; j += 256) {
        int p = j >> 3, seg = j & 7;
        unsigned short hv[8];
#pragma unroll
        for (int e = 0; e < 8; e++) {
            int cl = seg * 8 + e;
            int c = ic4 * 64 + cl;
            float v = sm[cl][p];
            float xl = ((v - mean) * istd) * lnw[c] + lnb[c];
            float z = fminf(fmaxf(xl * qs, -128.0f), 128.0f);
            hv[e] = __bfloat16_as_ushort(__float2bfloat16_rn(rintf(z)));
        }
        uint4 u;
        u.x = (uint32_t)hv[0] | ((uint32_t)hv[1] << 16);
        u.y = (uint32_t)hv[2] | ((uint32_t)hv[3] << 16);
        u.z = (uint32_t)hv[4] | ((uint32_t)hv[5] << 16);
        u.w = (uint32_t)hv[6] | ((uint32_t)hv[7] << 16);
        *(uint4*)(ob + (size_t)p * Cc + seg * 8) = u;
    }
}

// ---------------------------------------------------------------------------
// K3w: ternarize weights -> bf16 [tap][ic][oc]
// ---------------------------------------------------------------------------
__global__ void k_wq(const float* __restrict__ w) {
    int idx = blockIdx.x * 256 + threadIdx.x;       // 2304 blocks
    int tap = idx >> 16;
    int rem = idx & 65535;
    int ic = rem >> 8, oc = rem & 255;
    float v = w[(size_t)(oc * Cc + ic) * 9 + tap];
    float d = g_delta;
    float q = (v > d) ? 1.f : ((v < -d) ? -1.f : 0.f);
    g_wq[idx] = __float2bfloat16_rn(q);
}

// ---------------------------------------------------------------------------
// K4: implicit-GEMM conv via mma.sync.
// CTA: 128 pixels (2 output rows) x 256 oc.  K = 9 taps x 256 ic, chunk 32.
// 4-stage cp.async ring (24KB/stage); 8 warps 2(M) x 4(N); warp 64px x 64oc.
// ---------------------------------------------------------------------------
#define STAGES 4
#define STAGE_B 24576                 // 8KB A (128x32) + 16KB B (32x256)
#define CONV_SMEM (STAGES * STAGE_B)  // 96 KB, reused by epilogue (needs 64KB)

__global__ void __launch_bounds__(256)
k_conv(const float* __restrict__ bias, float* __restrict__ out) {
    extern __shared__ __align__(1024) char smem[];
    uint32_t sb = smem_u32(smem);
    float* sbuf = (float*)smem;

    int tid = threadIdx.x, lid = tid & 31, wid = tid >> 5;
    int wm = wid & 1, wn = wid >> 1;              // warp grid 2(M) x 4(N)
    int b = blockIdx.x;
    int rp = b & 31, n = b >> 5;
    int y0 = rp * 2;

    const __nv_bfloat16* xqn = g_xq + (size_t)n * PP * PP * Cc;

    // A staging coords (2 cp16/thread/stage)
    int apx0 = tid >> 2, ac0 = tid & 3;
    int apx1 = (tid + 256) >> 2;
    int aph0 = ac0 ^ ((apx0 >> 1) & 3);
    int aph1 = ac0 ^ ((apx1 >> 1) & 3);
    int aRow0 = y0 + (apx0 >> 6), aCol0 = apx0 & 63;
    int aRow1 = y0 + (apx1 >> 6), aCol1 = apx1 & 63;
    // B staging coords (4 cp16/thread/stage): rows bk0+8r, chunk bc, phase bph
    int bk0 = tid >> 5, bc = tid & 31;
    int bph = bc ^ (bk0 & 7);                     // (bk0+8r)&7 == bk0&7

    float d[4][8][4];
#pragma unroll
    for (int i = 0; i < 4; i++)
#pragma unroll
        for (int j = 0; j < 8; j++)
#pragma unroll
            for (int e = 0; e < 4; e++) d[i][j][e] = 0.f;

    auto stage = [&](int ch, int s) {
        if (ch < 72) {
            int tap = ch >> 3, icc = ch & 7;
            int ic0 = icc * 32;
            int ky = (tap >= 6) ? 2 : ((tap >= 3) ? 1 : 0);
            int kx = tap - ky * 3;
            uint32_t As = sb + s * STAGE_B;
            uint32_t Bs = As + 8192;
            cp16(As + apx0 * 64 + aph0 * 16,
                 xqn + ((size_t)(aRow0 + ky) * PP + aCol0 + kx) * Cc + ic0 + ac0 * 8);
            cp16(As + apx1 * 64 + aph1 * 16,
                 xqn + ((size_t)(aRow1 + ky) * PP + aCol1 + kx) * Cc + ic0 + ac0 * 8);
            const __nv_bfloat16* wsrc = g_wq + tap * 65536 + (ic0 + bk0) * 256 + bc * 8;
            uint32_t wdst = Bs + bk0 * 512 + bph * 16;
#pragma unroll
            for (int r = 0; r < 4; r++)
                cp16(wdst + r * 8 * 512, wsrc + r * 8 * 256);
        }
        cp_commit();
    };

    stage(0, 0); stage(1, 1); stage(2, 2);

    for (int it = 0; it < 72; it++) {
        __syncthreads();
        stage(it + 3, (it + 3) & 3);
        asm volatile("cp.async.wait_group 3;" ::: "memory");
        __syncthreads();

        uint32_t As = sb + (it & 3) * STAGE_B;
        uint32_t Bs = As + 8192;
#pragma unroll
        for (int g = 0; g < 2; g++) {
            uint32_t a[4][4];
#pragma unroll
            for (int i = 0; i < 4; i++) {
                int px = wm * 64 + i * 16 + (lid & 15);
                int kb = g * 2 + (lid >> 4);
                int ph = kb ^ ((px >> 1) & 3);
                ldsm_x4(As + px * 64 + ph * 16, a[i][0], a[i][1], a[i][2], a[i][3]);
            }
#pragma unroll
            for (int jj = 0; jj < 4; jj++) {
                uint32_t bf[4];
                int k = g * 16 + (lid & 15);
                int cb = wn * 8 + jj * 2 + (lid >> 4);
                int ph = cb ^ (k & 7);
                ldsm_x4t(Bs + k * 512 + ph * 16, bf[0], bf[1], bf[2], bf[3]);
#pragma unroll
                for (int i = 0; i < 4; i++) {
                    mma16816(d[i][jj * 2], a[i], bf[0], bf[1]);
                    mma16816(d[i][jj * 2 + 1], a[i], bf[2], bf[3]);
                }
            }
        }
    }
    asm volatile("cp.async.wait_group 0;" ::: "memory");
    __syncthreads();

    // ---- epilogue: two oc-half passes of smem transpose -> coalesced stores ----
    int wb = wid * 2048;                           // 8KB float region per warp
    int q = lid >> 2, t2 = (lid & 3) * 2;
    float coef = g_coef;
    int y = y0 + wm;
#pragma unroll
    for (int h = 0; h < 2; h++) {
#pragma unroll
        for (int jl = 0; jl < 4; jl++) {
            int j = h * 4 + jl;
#pragma unroll
            for (int i = 0; i < 4; i++) {
                int px = i * 16 + q;
                int ocl = jl * 8 + t2;
                sbuf[wb + ocl * 64 + px]           = d[i][j][0];
                sbuf[wb + (ocl + 1) * 64 + px]     = d[i][j][1];
                sbuf[wb + ocl * 64 + px + 8]       = d[i][j][2];
                sbuf[wb + (ocl + 1) * 64 + px + 8] = d[i][j][3];
            }
        }
        __syncwarp();
#pragma unroll
        for (int itr = 0; itr < 16; itr++) {
            int ocl = itr * 2 + (lid >> 4);
            int x4 = (lid & 15) * 4;
            float4 v = *(float4*)&sbuf[wb + ocl * 64 + x4];
            int oc = wn * 64 + h * 32 + ocl;
            float bz = bias[oc];
            v.x = v.x * coef + bz;
            v.y = v.y * coef + bz;
            v.z = v.z * coef + bz;
            v.w = v.w * coef + bz;
            *(float4*)(out + (((size_t)n * Cc + oc) * Hh + y) * Ww + x4) = v;
        }
        __syncwarp();
    }
}

// ---------------------------------------------------------------------------
// Host launch
// ---------------------------------------------------------------------------
extern "C" void kernel_launch(void* const* d_in, const int* in_sizes, int n_in,
                              void* d_out, int out_size) {
    const float* x    = (const float*)d_in[0];
    const float* w    = (const float*)d_in[1];
    const float* bias = (const float*)d_in[2];
    const float* lnw  = (const float*)d_in[3];
    const float* lnb  = (const float*)d_in[4];
    float* out = (float*)d_out;

    cudaFuncSetAttribute(k_conv, cudaFuncAttributeMaxDynamicSharedMemorySize, CONV_SMEM);

    k_init<<<1, 32>>>();
    k_stats<<<dim3(64, Nn), 256>>>(x);
    k_wabs<<<64, 256>>>(w);
    k_max<<<dim3(64, Nn), 256>>>(x, lnw, lnb);
    k_post<<<1, 32>>>();
    k_halo<<<520, 256>>>();
    k_quant_t<<<4096, 256>>>(x, lnw, lnb);
    k_wq<<<2304, 256>>>(w);
    k_conv<<<512, 256, CONV_SMEM>>>(bias, out);
}

// round 7
// speedup vs baseline: 1.3755x; 1.3755x over previous
#include <cuda_runtime.h>
#include <cuda_bf16.h>
#include <math.h>
#include <stdint.h>

// ---------------------------------------------------------------------------
// Problem constants
// ---------------------------------------------------------------------------
#define Nn   16
#define Cc   256
#define Hh   64
#define Ww   64
#define PP   66                       // padded spatial (1 halo each side)
#define NPIX (Cc*Hh*Ww)               // per-sample elements (GroupNorm group)
#define XQTOT (Nn*PP*PP*Cc)           // NHWC padded bf16 activations
#define WTOT (Cc*Cc*9)
#define GN_EPSF 1e-5f

// ---------------------------------------------------------------------------
// Scratch (__device__ globals; no allocation anywhere)
// ---------------------------------------------------------------------------
__device__ __align__(1024) __nv_bfloat16 g_xq[XQTOT];   // [n][ph][pw][ic]
__device__ __align__(1024) __nv_bfloat16 g_wq[WTOT];    // [tap][ic][oc], {-1,0,1}
__device__ double g_sum[Nn];
__device__ double g_sumsq[Nn];
__device__ double g_wabs;
__device__ float g_cmin[Nn*Cc], g_cmax[Nn*Cc];          // per-(n,c) extremes of x
__device__ float g_meanf[Nn], g_istdf[Nn];
__device__ float g_qscale;   // 128 / gamma
__device__ float g_coef;     // 0.01 * gamma / 128
__device__ float g_delta;    // 0.7 * mean|w|

// ---------------------------------------------------------------------------
// Portable PTX helpers (sm_80+ only; must compile under plain sm_100)
// ---------------------------------------------------------------------------
__device__ __forceinline__ uint32_t smem_u32(const void* p) {
    uint32_t a;
    asm("{ .reg .u64 t; cvta.to.shared.u64 t, %1; cvt.u32.u64 %0, t; }" : "=r"(a) : "l"(p));
    return a;
}
__device__ __forceinline__ void cp16(uint32_t dst, const void* src) {
    asm volatile("cp.async.cg.shared.global [%0], [%1], 16;" :: "r"(dst), "l"(src) : "memory");
}
__device__ __forceinline__ void cp_commit() {
    asm volatile("cp.async.commit_group;" ::: "memory");
}
__device__ __forceinline__ void ldsm_x4(uint32_t a, uint32_t& r0, uint32_t& r1,
                                        uint32_t& r2, uint32_t& r3) {
    asm volatile("ldmatrix.sync.aligned.m8n8.x4.shared.b16 {%0,%1,%2,%3}, [%4];"
                 : "=r"(r0), "=r"(r1), "=r"(r2), "=r"(r3) : "r"(a));
}
__device__ __forceinline__ void ldsm_x4t(uint32_t a, uint32_t& r0, uint32_t& r1,
                                         uint32_t& r2, uint32_t& r3) {
    asm volatile("ldmatrix.sync.aligned.m8n8.x4.trans.shared.b16 {%0,%1,%2,%3}, [%4];"
                 : "=r"(r0), "=r"(r1), "=r"(r2), "=r"(r3) : "r"(a));
}
__device__ __forceinline__ void mma16816(float* d, const uint32_t* a,
                                         uint32_t b0, uint32_t b1) {
    asm volatile(
        "mma.sync.aligned.m16n8k16.row.col.f32.bf16.bf16.f32 "
        "{%0,%1,%2,%3}, {%4,%5,%6,%7}, {%8,%9}, {%0,%1,%2,%3};"
        : "+f"(d[0]), "+f"(d[1]), "+f"(d[2]), "+f"(d[3])
        : "r"(a[0]), "r"(a[1]), "r"(a[2]), "r"(a[3]), "r"(b0), "r"(b1));
}

// ---------------------------------------------------------------------------
// K0: zero reduction scratch
// ---------------------------------------------------------------------------
__global__ void k_init() {
    int t = threadIdx.x;
    if (t < Nn) { g_sum[t] = 0.0; g_sumsq[t] = 0.0; }
    if (t == 0) { g_wabs = 0.0; }
}

// ---------------------------------------------------------------------------
// K1: per-sample sum / sumsq + exact per-(n,c) min/max of x.
// Each block covers exactly 4 whole channels (16384 contiguous elems).
// ---------------------------------------------------------------------------
__global__ void k_stats(const float* __restrict__ x) {
    int n = blockIdx.y;
    const float* p = x + (size_t)n * NPIX + (size_t)blockIdx.x * 16384;
    int tid = threadIdx.x;
    float s = 0.f, ss = 0.f;
    float mn[4] = {3.4e38f, 3.4e38f, 3.4e38f, 3.4e38f};
    float mx[4] = {-3.4e38f, -3.4e38f, -3.4e38f, -3.4e38f};
#pragma unroll
    for (int k = 0; k < 16; k++) {
        int ch = k >> 2;                       // constant per unrolled iter
        float4 v = *(const float4*)(p + tid * 4 + k * 1024);
        s  += v.x + v.y + v.z + v.w;
        ss += v.x*v.x + v.y*v.y + v.z*v.z + v.w*v.w;
        mn[ch] = fminf(mn[ch], fminf(fminf(v.x, v.y), fminf(v.z, v.w)));
        mx[ch] = fmaxf(mx[ch], fmaxf(fmaxf(v.x, v.y), fmaxf(v.z, v.w)));
    }
#pragma unroll
    for (int off = 16; off; off >>= 1) {
        s  += __shfl_xor_sync(0xffffffffu, s,  off);
        ss += __shfl_xor_sync(0xffffffffu, ss, off);
#pragma unroll
        for (int j = 0; j < 4; j++) {
            mn[j] = fminf(mn[j], __shfl_xor_sync(0xffffffffu, mn[j], off));
            mx[j] = fmaxf(mx[j], __shfl_xor_sync(0xffffffffu, mx[j], off));
        }
    }
    __shared__ double ws[8], wss[8];
    __shared__ float smn[8][4], smx[8][4];
    int wid = tid >> 5, lane = tid & 31;
    if (lane == 0) {
        ws[wid] = (double)s; wss[wid] = (double)ss;
#pragma unroll
        for (int j = 0; j < 4; j++) { smn[wid][j] = mn[j]; smx[wid][j] = mx[j]; }
    }
    __syncthreads();
    if (tid == 0) {
        double S = 0.0, SS = 0.0;
#pragma unroll
        for (int i = 0; i < 8; i++) { S += ws[i]; SS += wss[i]; }
        atomicAdd(&g_sum[n], S);
        atomicAdd(&g_sumsq[n], SS);
    }
    if (tid < 4) {
        float a = 3.4e38f, bmax = -3.4e38f;
#pragma unroll
        for (int w = 0; w < 8; w++) {
            a = fminf(a, smn[w][tid]);
            bmax = fmaxf(bmax, smx[w][tid]);
        }
        int c = blockIdx.x * 4 + tid;
        g_cmin[n * Cc + c] = a;
        g_cmax[n * Cc + c] = bmax;
    }
}

// ---------------------------------------------------------------------------
// K1w: sum |w|
// ---------------------------------------------------------------------------
__global__ void k_wabs(const float* __restrict__ w) {
    int tid = threadIdx.x;
    float s = 0.f;
    for (int i = blockIdx.x * 256 + tid; i < WTOT; i += gridDim.x * 256)
        s += fabsf(w[i]);
#pragma unroll
    for (int off = 16; off; off >>= 1) s += __shfl_xor_sync(0xffffffffu, s, off);
    __shared__ double ws[8];
    int wid = tid >> 5, lane = tid & 31;
    if (lane == 0) ws[wid] = (double)s;
    __syncthreads();
    if (tid == 0) {
        double S = 0.0;
#pragma unroll
        for (int i = 0; i < 8; i++) S += ws[i];
        atomicAdd(&g_wabs, S);
    }
}

__device__ __forceinline__ void sample_stats(int n, float& fm, float& istd) {
    double S = g_sum[n], SS = g_sumsq[n];
    double m = S * (1.0 / (double)NPIX);
    double v = SS * (1.0 / (double)NPIX) - m * m;
    fm = (float)m;
    istd = 1.0f / sqrtf((float)v + GN_EPSF);
}

// ---------------------------------------------------------------------------
// K2: finalize scalars.  gamma from per-channel endpoints (affine GroupNorm
// is monotone in x per (n,c), so |.| max is at an endpoint; identical fp
// formula applied to actual data values -> bit-identical to elementwise max).
// ---------------------------------------------------------------------------
__global__ void k_post(const float* __restrict__ lnw, const float* __restrict__ lnb) {
    __shared__ float sm[Nn], si[Nn];
    __shared__ float wred[8];
    int tid = threadIdx.x;
    if (tid < Nn) {
        float fm, istd;
        sample_stats(tid, fm, istd);
        g_meanf[tid] = fm; g_istdf[tid] = istd;
        sm[tid] = fm; si[tid] = istd;
    }
    __syncthreads();
    float m = 0.f;
#pragma unroll
    for (int it = 0; it < 16; it++) {
        int idx = it * 256 + tid;
        int n = idx >> 8, c = idx & 255;
        float fm = sm[n], istd = si[n], g = lnw[c], bb = lnb[c];
        m = fmaxf(m, fabsf(((g_cmin[idx] - fm) * istd) * g + bb));
        m = fmaxf(m, fabsf(((g_cmax[idx] - fm) * istd) * g + bb));
    }
#pragma unroll
    for (int off = 16; off; off >>= 1) m = fmaxf(m, __shfl_xor_sync(0xffffffffu, m, off));
    int wid = tid >> 5, lane = tid & 31;
    if (lane == 0) wred[wid] = m;
    __syncthreads();
    if (tid == 0) {
#pragma unroll
        for (int i = 1; i < 8; i++) m = fmaxf(m, wred[i]);
        float gamma = fmaxf(m, 1e-6f);
        g_qscale = 128.0f / gamma;
        g_coef = 0.01f * gamma * (1.0f / 128.0f);
        g_delta = 0.7f * (float)(g_wabs * (1.0 / (double)WTOT));
    }
}

// ---------------------------------------------------------------------------
// K3a: zero the halo of g_xq
// ---------------------------------------------------------------------------
__global__ void k_halo() {
    int idx = blockIdx.x * 256 + threadIdx.x;       // 520 blocks
    int n = idx / (260 * 32);
    int r = idx - n * (260 * 32);
    int p = r >> 5, q = r & 31;
    int ph, pw;
    if (p < 66)       { ph = 0;       pw = p; }
    else if (p < 132) { ph = 65;      pw = p - 66; }
    else if (p < 196) { ph = p - 131; pw = 0; }
    else              { ph = p - 195; pw = 65; }
    uint4 z = make_uint4(0, 0, 0, 0);
    *(uint4*)(g_xq + ((size_t)(n * PP + ph) * PP + pw) * Cc + q * 8) = z;
}

// ---------------------------------------------------------------------------
// K3: quantize + NCHW->NHWC transpose into padded bf16 scratch
// ---------------------------------------------------------------------------
__global__ void k_quant_t(const float* __restrict__ x,
                          const float* __restrict__ lnw,
                          const float* __restrict__ lnb) {
    __shared__ float sm[64][68];
    int b = blockIdx.x;
    int ic4 = b & 3, h = (b >> 2) & 63, n = b >> 8;
    int tid = threadIdx.x;
    float mean = g_meanf[n], istd = g_istdf[n], qs = g_qscale;

    const float* xb = x + ((size_t)n * Cc + ic4 * 64) * 4096 + h * 64;
#pragma unroll
    for (int i = tid; i < 1024; i += 256) {
        int row = i >> 4, c4 = i & 15;
        float4 v = *(const float4*)(xb + (size_t)row * 4096 + c4 * 4);
        *(float4*)&sm[row][c4 * 4] = v;
    }
    __syncthreads();

    __nv_bfloat16* ob = g_xq + ((size_t)(n * PP + h + 1) * PP + 1) * Cc + ic4 * 64;
#pragma unroll
    for (int j = tid; j < 512; j += 256) {
        int p = j >> 3, seg = j & 7;
        unsigned short hv[8];
#pragma unroll
        for (int e = 0; e < 8; e++) {
            int cl = seg * 8 + e;
            int c = ic4 * 64 + cl;
            float v = sm[cl][p];
            float xl = ((v - mean) * istd) * lnw[c] + lnb[c];
            float z = fminf(fmaxf(xl * qs, -128.0f), 128.0f);
            hv[e] = __bfloat16_as_ushort(__float2bfloat16_rn(rintf(z)));
        }
        uint4 u;
        u.x = (uint32_t)hv[0] | ((uint32_t)hv[1] << 16);
        u.y = (uint32_t)hv[2] | ((uint32_t)hv[3] << 16);
        u.z = (uint32_t)hv[4] | ((uint32_t)hv[5] << 16);
        u.w = (uint32_t)hv[6] | ((uint32_t)hv[7] << 16);
        *(uint4*)(ob + (size_t)p * Cc + seg * 8) = u;
    }
}

// ---------------------------------------------------------------------------
// K3w: ternarize weights -> bf16 [tap][ic][oc]
// ---------------------------------------------------------------------------
__global__ void k_wq(const float* __restrict__ w) {
    int idx = blockIdx.x * 256 + threadIdx.x;       // 2304 blocks
    int tap = idx >> 16;
    int rem = idx & 65535;
    int ic = rem >> 8, oc = rem & 255;
    float v = w[(size_t)(oc * Cc + ic) * 9 + tap];
    float d = g_delta;
    float q = (v > d) ? 1.f : ((v < -d) ? -1.f : 0.f);
    g_wq[idx] = __float2bfloat16_rn(q);
}

// ---------------------------------------------------------------------------
// K4: implicit-GEMM conv via mma.sync with kx tap-reuse A strips.
// CTA: 128 px (2 rows x 64 cols) x 128 oc.  24 chunks = ky(3) x ic-chunk(8).
// Per chunk: one 2x66-px A strip (covers kx=0..2) + 3 B tap-tiles.
// 3-stage cp.async ring; 8 warps 2(M) x 4(N); warp 64px x 32oc; 64 accums.
// ---------------------------------------------------------------------------
#define STAGES 3
#define A_BYTES 8448                  // 132 strip-px * 64 B
#define STAGE_B (A_BYTES + 3 * 8192)  // 33024
#define CONV_SMEM (STAGES * STAGE_B)  // 99072; epilogue reuse needs 64KB

__global__ void __launch_bounds__(256, 2)
k_conv(const float* __restrict__ bias, float* __restrict__ out) {
    extern __shared__ __align__(1024) char smem[];
    uint32_t sb = smem_u32(smem);
    float* sbuf = (float*)smem;

    int tid = threadIdx.x, lid = tid & 31, wid = tid >> 5;
    int wm = wid & 1, wn = wid >> 1;              // warp grid 2(M) x 4(N)
    int b = blockIdx.x;
    int ocb = b & 1, rp = (b >> 1) & 31, n = b >> 6;
    int y0 = rp * 2, ocBase = ocb * 128;

    const __nv_bfloat16* xqn = g_xq + (size_t)n * PP * PP * Cc;

    int bk0 = tid >> 4, bc0 = tid & 15;           // B staging coords
    uint32_t bsw = (uint32_t)(bc0 ^ (bk0 & 7)) << 4;

    float d[4][4][4];
#pragma unroll
    for (int i = 0; i < 4; i++)
#pragma unroll
        for (int j = 0; j < 4; j++)
#pragma unroll
            for (int e = 0; e < 4; e++) d[i][j][e] = 0.f;

    auto stage = [&](int ch, int s) {
        if (ch < 24) {
            int ky = ch >> 3, icc = ch & 7;
            int ic0 = icc * 32;
            uint32_t As = sb + s * STAGE_B;
            uint32_t Bs = As + A_BYTES;
            // A strip: 132 px (2 rows x 66 cols) x 32 ic = 528 cp16
#pragma unroll
            for (int rr = 0; rr < 3; rr++) {
                int idx = tid + rr * 256;
                if (rr < 2 || tid < 16) {
                    int px = idx >> 2, c = idx & 3;
                    int row = (px >= 66) ? 1 : 0;
                    int col = px - row * 66;
                    cp16(As + px * 64 + ((c ^ ((px >> 1) & 3)) << 4),
                         xqn + ((size_t)(y0 + ky + row) * PP + col) * Cc + ic0 + c * 8);
                }
            }
            // B: 3 kx taps, each 32 ic x 128 oc (R4-proven layout per tap)
#pragma unroll
            for (int t = 0; t < 3; t++) {
                const __nv_bfloat16* wb =
                    g_wq + (size_t)(ky * 3 + t) * 65536 + (size_t)ic0 * 256 + ocBase + bc0 * 8;
                uint32_t Bt = Bs + t * 8192;
                cp16(Bt + bk0 * 256 + bsw, wb + (size_t)bk0 * 256);
                cp16(Bt + (bk0 + 16) * 256 + bsw, wb + (size_t)(bk0 + 16) * 256);
            }
        }
        cp_commit();
    };

    stage(0, 0); stage(1, 1);

    int sc = 0, sp = 2;                            // consume slot, produce slot
    for (int it = 0; it < 24; it++) {
        __syncthreads();
        stage(it + 2, sp);
        asm volatile("cp.async.wait_group 2;" ::: "memory");
        __syncthreads();

        uint32_t As = sb + sc * STAGE_B;
        uint32_t Bs = As + A_BYTES;
#pragma unroll
        for (int kx = 0; kx < 3; kx++) {
            uint32_t Bt = Bs + kx * 8192;
#pragma unroll
            for (int g = 0; g < 2; g++) {
                uint32_t a[4][4];
#pragma unroll
                for (int i = 0; i < 4; i++) {
                    int px = wm * 64 + i * 16 + (lid & 15);
                    int pxs = (px >> 6) * 66 + (px & 63) + kx;
                    int kb = g * 2 + (lid >> 4);
                    int ph = kb ^ ((pxs >> 1) & 3);
                    ldsm_x4(As + pxs * 64 + ph * 16, a[i][0], a[i][1], a[i][2], a[i][3]);
                }
#pragma unroll
                for (int jj = 0; jj < 2; jj++) {
                    uint32_t bf[4];
                    int k = g * 16 + (lid & 15);
                    int cb = wn * 4 + jj * 2 + (lid >> 4);
                    int ph = cb ^ (k & 7);
                    ldsm_x4t(Bt + k * 256 + ph * 16, bf[0], bf[1], bf[2], bf[3]);
#pragma unroll
                    for (int i = 0; i < 4; i++) {
                        mma16816(d[i][jj * 2], a[i], bf[0], bf[1]);
                        mma16816(d[i][jj * 2 + 1], a[i], bf[2], bf[3]);
                    }
                }
            }
        }
        if (++sc == 3) sc = 0;
        if (++sp == 3) sp = 0;
    }
    asm volatile("cp.async.wait_group 0;" ::: "memory");
    __syncthreads();

    // ---- epilogue: per-warp smem transpose -> coalesced NCHW float4 stores ----
    int wb = wid * 2048;                           // 8KB float region per warp
    int q = lid >> 2, t2 = (lid & 3) * 2;
#pragma unroll
    for (int i = 0; i < 4; i++) {
#pragma unroll
        for (int j = 0; j < 4; j++) {
            int px = i * 16 + q;
            int oc = j * 8 + t2;
            sbuf[wb + oc * 64 + px]           = d[i][j][0];
            sbuf[wb + (oc + 1) * 64 + px]     = d[i][j][1];
            sbuf[wb + oc * 64 + px + 8]       = d[i][j][2];
            sbuf[wb + (oc + 1) * 64 + px + 8] = d[i][j][3];
        }
    }
    __syncwarp();
    float coef = g_coef;
    int y = y0 + wm;
#pragma unroll
    for (int itr = 0; itr < 16; itr++) {
        int ocl = itr * 2 + (lid >> 4);
        int x4 = (lid & 15) * 4;
        float4 v = *(float4*)&sbuf[wb + ocl * 64 + x4];
        int oc = ocBase + wn * 32 + ocl;
        float bz = bias[oc];
        v.x = v.x * coef + bz;
        v.y = v.y * coef + bz;
        v.z = v.z * coef + bz;
        v.w = v.w * coef + bz;
        *(float4*)(out + (((size_t)n * Cc + oc) * Hh + y) * Ww + x4) = v;
    }
}

// ---------------------------------------------------------------------------
// Host launch
// ---------------------------------------------------------------------------
extern "C" void kernel_launch(void* const* d_in, const int* in_sizes, int n_in,
                              void* d_out, int out_size) {
    const float* x    = (const float*)d_in[0];
    const float* w    = (const float*)d_in[1];
    const float* bias = (const float*)d_in[2];
    const float* lnw  = (const float*)d_in[3];
    const float* lnb  = (const float*)d_in[4];
    float* out = (float*)d_out;

    cudaFuncSetAttribute(k_conv, cudaFuncAttributeMaxDynamicSharedMemorySize, CONV_SMEM);

    k_init<<<1, 32>>>();
    k_stats<<<dim3(64, Nn), 256>>>(x);
    k_wabs<<<64, 256>>>(w);
    k_post<<<1, 256>>>(lnw, lnb);
    k_halo<<<520, 256>>>();
    k_quant_t<<<4096, 256>>>(x, lnw, lnb);
    k_wq<<<2304, 256>>>(w);
    k_conv<<<1024, 256, CONV_SMEM>>>(bias, out);
}